// round 5
// baseline (speedup 1.0000x reference)
#include <cuda_runtime.h>
#include <math.h>

#define NB 512   // batch
#define NF 512   // features
#define NS 255   // splits
#define NN 511   // nodes
#define NC 21    // candidates

#define QSCALE 268435456.0                 // 2^28
#define QINV   3.7252902984619140625e-09f  // 2^-28

// ---------------- scratch (no allocations allowed) ----------------
__device__ unsigned long long g_qsplitI[NS * NB]; // [s][b] fixed-point accum (re-zeroed by scan_kernel's idle warps)
__device__ float g_qnodeT[NN * NB];               // [n][b]
__device__ float g_ga    [NN * NC];
__device__ float g_anode [NN];

// pack two floats into a 64-bit register for f32x2 ops
__device__ __forceinline__ unsigned long long pack2(float x, float y)
{
    unsigned long long r;
    asm("mov.b64 %0, {%1, %2};" : "=l"(r) : "f"(x), "f"(y));
    return r;
}
__device__ __forceinline__ void unpack2(unsigned long long v, float& x, float& y)
{
    asm("mov.b64 {%0, %1}, %2;" : "=f"(x), "=f"(y) : "l"(v));
}

// ================= kernel 1: split-K GEMM (f32x2 FMA), transposed output =================
// qsplitT[s][b] = sum_f W[f][s] * x[b][f]; grid (ksplit=8, bTile=8, sTile=4), 256 thr.
// Deterministic across replays: fixed-point int64 atomic accumulation.
__global__ __launch_bounds__(256, 2)
void gemm_kernel(const float* __restrict__ x, const float* __restrict__ W)
{
    __shared__ float As[64][68];   // [f][s]
    __shared__ float Bs[64][68];   // [f][b]  (row base 16B-aligned: 68*4=272)

    int tid   = threadIdx.x;
    int k0    = blockIdx.x * 64;
    int bBase = blockIdx.y * 64;
    int sBase = blockIdx.z * 64;

    {
        int s = tid & 63, f0 = tid >> 6;
        int gs = sBase + s;
#pragma unroll
        for (int i = 0; i < 16; i++) {
            int f = f0 + i * 4;
            As[f][s] = (gs < NS) ? W[(k0 + f) * NS + gs] : 0.0f;
        }
        int fb = tid & 63, b0 = tid >> 6;
#pragma unroll
        for (int i = 0; i < 16; i++) {
            int b = b0 + i * 4;
            Bs[fb][b] = x[(bBase + b) * NF + k0 + fb];
        }
    }
    __syncthreads();

    int tr = tid >> 4;   // s quad
    int tc = tid & 15;   // b quad

    unsigned long long acc[4][2];  // [s-idx][b-pair], each f32x2
#pragma unroll
    for (int i = 0; i < 4; i++) { acc[i][0] = 0ULL; acc[i][1] = 0ULL; }

#pragma unroll
    for (int f = 0; f < 64; f++) {
        float4 a4 = *(const float4*)&As[f][tr * 4];
        const ulonglong2 b2 = *(const ulonglong2*)&Bs[f][tc * 4];  // (b0,b1),(b2,b3)
        unsigned long long aa[4];
        aa[0] = pack2(a4.x, a4.x); aa[1] = pack2(a4.y, a4.y);
        aa[2] = pack2(a4.z, a4.z); aa[3] = pack2(a4.w, a4.w);
#pragma unroll
        for (int i = 0; i < 4; i++) {
            asm("fma.rn.f32x2 %0, %1, %2, %0;" : "+l"(acc[i][0]) : "l"(aa[i]), "l"(b2.x));
            asm("fma.rn.f32x2 %0, %1, %2, %0;" : "+l"(acc[i][1]) : "l"(aa[i]), "l"(b2.y));
        }
    }

#pragma unroll
    for (int i = 0; i < 4; i++) {
        int s = sBase + tr * 4 + i;
        if (s < NS) {
            float v[4];
            unpack2(acc[i][0], v[0], v[1]);
            unpack2(acc[i][1], v[2], v[3]);
#pragma unroll
            for (int j = 0; j < 4; j++) {
                int b = bBase + tc * 4 + j;
                long long q = __double2ll_rn((double)v[j] * QSCALE);
                atomicAdd(&g_qsplitI[s * NB + b], (unsigned long long)q);
            }
        }
    }
}

// ================= kernel 2: q_node (ancestor walk) + g_a reduction =================
__global__ __launch_bounds__(256)
void ga_kernel(const float* __restrict__ bias)
{
    __shared__ float sBias[256];
    __shared__ float sP[256 * NC];   // [tid][c], stride 21 (odd) -> conflict-free

    int n   = blockIdx.x;
    int tid = threadIdx.x;
    if (tid < NS) sBias[tid] = bias[tid];
    __syncthreads();

    float accs[NC];
#pragma unroll
    for (int c = 0; c < NC; c++) accs[c] = 0.0f;

#pragma unroll
    for (int rep = 0; rep < 2; rep++) {
        int b = tid + rep * 256;
        float m = 1.0f;
        int a = n;
        while (a > 0) {
            int p = (a - 1) >> 1;
            float q = (float)(long long)g_qsplitI[p * NB + b] * QINV + sBias[p];
            m = fminf(m, (a == 2 * p + 1) ? -q : q);
            a = p;
        }
        g_qnodeT[n * NB + b] = m;
        float qh = m + 0.5f;
#pragma unroll
        for (int c = 0; c < NC; c++) {
            float d = fminf((float)c * (1.0f / 20.0f) - qh, 0.0f);
            accs[c] = fmaf(d, d, accs[c]);
        }
    }

#pragma unroll
    for (int c = 0; c < NC; c++) sP[tid * NC + c] = accs[c];
    __syncthreads();

    // warp w reduces candidates c = w*3+q (q<3), over 256 rows
    int w = tid >> 5, l = tid & 31;
#pragma unroll
    for (int q = 0; q < 3; q++) {
        int c = w * 3 + q;
        if (c < NC) {
            float s = 0.0f;
#pragma unroll
            for (int r = 0; r < 8; r++) s += sP[(l + 32 * r) * NC + c];
#pragma unroll
            for (int o = 16; o > 0; o >>= 1) s += __shfl_down_sync(0xffffffffu, s, o);
            if (l == 0) {
                float ac = (float)c * (1.0f / 20.0f);
                g_ga[n * NC + c] = 0.5f * ac * ac + 0.5f * s;
            }
        }
    }
}

// ================= kernel 3: the scan (warp-serial, conflict-free, sAnode cache) =================
__device__ __forceinline__ void softmin_warp(int g, const float* sGa, const int* sK, float* sAgrp)
{
    int lane = threadIdx.x & 31;
    float kg = (float)sK[g];
    int c1 = 2 * g + 1, c2 = 2 * g + 2;
    float s;
    if (lane < NC) {
        float v = (1.0f - kg) * sGa[g * NC + lane];
        if (c1 < NN) v += (float)sK[c1] * sGa[c1 * NC + lane];
        if (c2 < NN) v += (float)sK[c2] * sGa[c2 * NC + lane];
        s = -100.0f * v;
    } else {
        s = -3.0e38f;
    }
    float m = s;
#pragma unroll
    for (int o = 16; o > 0; o >>= 1) m = fmaxf(m, __shfl_xor_sync(0xffffffffu, m, o));
    float e  = (lane < NC) ? __expf(s - m) : 0.0f;
    float ae = e * ((float)lane * (1.0f / 20.0f));
#pragma unroll
    for (int o = 16; o > 0; o >>= 1) {
        e  += __shfl_xor_sync(0xffffffffu, e, o);
        ae += __shfl_xor_sync(0xffffffffu, ae, o);
    }
    if (lane == 0) sAgrp[g] = ae / e;
}

__global__ __launch_bounds__(256)
void scan_kernel()
{
    __shared__ float sGa[NN * NC];   // 42924 B
    __shared__ float sAgrp[NN];
    __shared__ float sAnode[NN];
    __shared__ int   sK[NN];         // total 49056 B < 48KB static cap

    int tid = threadIdx.x;

    for (int i = tid; i < NN * NC; i += 256) sGa[i] = g_ga[i];
    for (int i = tid; i < NN; i += 256) sK[i] = 0;
    __syncthreads();

    // initial a_grp (k==0 -> own-row softmin); a_node == a_grp initially
    for (int i = tid; i < NN; i += 256) {
        const float* r = &sGa[i * NC];
        float m = -3.0e38f;
#pragma unroll
        for (int c = 0; c < NC; c++) m = fmaxf(m, -100.0f * r[c]);
        float su = 0.0f, asu = 0.0f;
#pragma unroll
        for (int c = 0; c < NC; c++) {
            float e = __expf(-100.0f * r[c] - m);
            su += e; asu += (float)c * (1.0f / 20.0f) * e;
        }
        float ag = asu / su;
        sAgrp[i]  = ag;
        sAnode[i] = ag;
    }
    __syncthreads();

    if (tid < 32) {
        // warp 0: the merge loop. interleaved node assignment -> conflict-free LDS.
        int lane = tid;
        int applied = 0;
        for (;;) {
            float bv = -3.0e38f; int bi = NN;
#pragma unroll
            for (int i = 0; i < 16; i++) {
                int n = i * 32 + lane;
                if (n < NN) {
                    float an = sAnode[n];
                    float ap = (n == 0) ? 1.0f : sAnode[(n - 1) >> 1];
                    float v = an - ap;
                    if (v > bv || (v == bv && n < bi)) { bv = v; bi = n; }
                }
            }
#pragma unroll
            for (int o = 16; o > 0; o >>= 1) {
                float ov = __shfl_down_sync(0xffffffffu, bv, o);
                int   oi = __shfl_down_sync(0xffffffffu, bi, o);
                if (ov > bv || (ov == bv && oi < bi)) { bv = ov; bi = oi; }
            }
            int t = (lane == 0) ? ((bv <= 1e-8f && bi > 0) ? bi : -1) : 0;
            t = __shfl_sync(0xffffffffu, t, 0);
            if (t < 0 || applied >= NN) break;   // fixed point / 512th body's merge discarded
            applied++;
            if (lane == 0) sK[t] += 1;
            __syncwarp();
            int p = (t - 1) >> 1;
            softmin_warp(p, sGa, sK, sAgrp);
            __syncwarp();
            softmin_warp(t, sGa, sK, sAgrp);
            __syncwarp();
            // incremental a_node refresh: exactly {p, t, sib(t), 2t+1, 2t+2}
            if (lane < 5) {
                int s0 = 2 * p + 1, s1 = 2 * p + 2;
                int sib = (s0 == t) ? s1 : s0;
                int m = (lane == 0) ? p
                      : (lane == 1) ? t
                      : (lane == 2) ? sib
                      : (lane == 3) ? 2 * t + 1
                                    : 2 * t + 2;
                if (m < NN) {
                    float an;
                    if (m == 0) an = sAgrp[0];
                    else {
                        float k = (float)sK[m];
                        an = (1.0f - k) * sAgrp[m] + k * sAgrp[(m - 1) >> 1];
                    }
                    sAnode[m] = an;
                }
            }
            __syncwarp();
        }
    } else {
        // idle warps: re-zero the GEMM fixed-point accumulator (overlapped with the scan)
        ulonglong2 z; z.x = 0ULL; z.y = 0ULL;
        ulonglong2* p = (ulonglong2*)g_qsplitI;
        for (int i = tid - 32; i < NS * NB / 2; i += 224) p[i] = z;
    }
    __syncthreads();

    for (int i = tid; i < NN; i += 256) g_anode[i] = sAnode[i];
}

// ================= kernel 4: transposed trajectory =================
// 256 blocks, one 32x32 tile each; coalesced load AND store.
__global__ __launch_bounds__(256)
void traj_kernel(float* __restrict__ out)
{
    __shared__ float tile[32][33];
    int tid = threadIdx.x;
    int tn = blockIdx.x >> 4, tb = blockIdx.x & 15;
    int n0 = tn * 32, b0 = tb * 32;

#pragma unroll
    for (int pass = 0; pass < 4; pass++) {
        int r = (tid >> 5) + pass * 8, c = tid & 31;
        int n = n0 + r;
        float v = 0.0f;
        if (n < NN) {
            float q = g_qnodeT[n * NB + b0 + c];          // coalesced over b
            v = fminf(fmaxf(q, 0.0f), g_anode[n]);
        }
        tile[r][c] = v;
    }
    __syncthreads();
#pragma unroll
    for (int pass = 0; pass < 4; pass++) {
        int r = (tid >> 5) + pass * 8, c = tid & 31;
        int n = n0 + c;
        if (n < NN) out[(b0 + r) * NN + n] = tile[c][r];  // coalesced over n
    }
}

// ---------------- launch ----------------
extern "C" void kernel_launch(void* const* d_in, const int* in_sizes, int n_in,
                              void* d_out, int out_size)
{
    const float* x = (const float*)d_in[0];
    const float* W = (const float*)d_in[1];
    const float* b = (const float*)d_in[2];
    // d_in[3] = max_depth (fixed at 8; shapes hardcoded)

    gemm_kernel<<<dim3(8, 8, 4), 256>>>(x, W);
    ga_kernel  <<<NN, 256>>>(b);
    scan_kernel<<<1, 256>>>();
    traj_kernel<<<256, 256>>>((float*)d_out);
}

// round 6
// speedup vs baseline: 1.4155x; 1.4155x over previous
#include <cuda_runtime.h>
#include <math.h>

#define NB 512   // batch
#define NF 512   // features
#define NS 255   // splits
#define NN 511   // nodes
#define NC 21    // candidates

#define QSCALE 268435456.0                 // 2^28
#define QINV   3.7252902984619140625e-09f  // 2^-28

// ---------------- scratch (no allocations allowed) ----------------
__device__ unsigned long long g_qsplitI[NS * NB]; // [s][b] fixed-point accum (re-zeroed by traj_kernel)
__device__ float g_qnodeT[NN * NB];               // [n][b]
__device__ float g_ga    [NN * NC];
__device__ float g_anode [NN];

// ================= kernel 1: split-K GEMM, transposed output =================
// qsplitT[s][b] = sum_f W[f][s] * x[b][f]   (bias added by consumers)
// grid: (ksplit=8, bTile=8, sTile=4), block 256, each block 64x64x64 panel.
// Deterministic: fixed-point int64 atomic accumulation.
__global__ __launch_bounds__(256, 2)
void gemm_kernel(const float* __restrict__ x, const float* __restrict__ W)
{
    __shared__ float As[64][68];   // [f][s]
    __shared__ float Bs[64][68];   // [f][b]

    int tid   = threadIdx.x;
    int k0    = blockIdx.x * 64;
    int bBase = blockIdx.y * 64;
    int sBase = blockIdx.z * 64;

    {
        int s = tid & 63, f0 = tid >> 6;
        int gs = sBase + s;
#pragma unroll
        for (int i = 0; i < 16; i++) {
            int f = f0 + i * 4;
            As[f][s] = (gs < NS) ? W[(k0 + f) * NS + gs] : 0.0f;
        }
        int fb = tid & 63, b0 = tid >> 6;
#pragma unroll
        for (int i = 0; i < 16; i++) {
            int b = b0 + i * 4;
            Bs[fb][b] = x[(bBase + b) * NF + k0 + fb];
        }
    }
    __syncthreads();

    int tr = tid >> 4;   // s quad
    int tc = tid & 15;   // b quad
    float acc[4][4];
#pragma unroll
    for (int i = 0; i < 4; i++)
#pragma unroll
        for (int j = 0; j < 4; j++) acc[i][j] = 0.0f;

#pragma unroll
    for (int f = 0; f < 64; f++) {
        float4 a4 = *(const float4*)&As[f][tr * 4];
        float4 b4 = *(const float4*)&Bs[f][tc * 4];
        float av[4] = {a4.x, a4.y, a4.z, a4.w};
        float bv[4] = {b4.x, b4.y, b4.z, b4.w};
#pragma unroll
        for (int i = 0; i < 4; i++)
#pragma unroll
            for (int j = 0; j < 4; j++) acc[i][j] += av[i] * bv[j];
    }

#pragma unroll
    for (int i = 0; i < 4; i++) {
        int s = sBase + tr * 4 + i;
        if (s < NS) {
#pragma unroll
            for (int j = 0; j < 4; j++) {
                int b = bBase + tc * 4 + j;
                long long q = __double2ll_rn((double)acc[i][j] * QSCALE);
                atomicAdd(&g_qsplitI[s * NB + b], (unsigned long long)q);
            }
        }
    }
}

// ================= kernel 2: q_node (ancestor walk) + g_a reduction =================
__global__ __launch_bounds__(256)
void ga_kernel(const float* __restrict__ bias)
{
    int n   = blockIdx.x;
    int tid = threadIdx.x;

    float accs[NC];
#pragma unroll
    for (int c = 0; c < NC; c++) accs[c] = 0.0f;

#pragma unroll
    for (int rep = 0; rep < 2; rep++) {
        int b = tid + rep * 256;
        float m = 1.0f;
        int a = n;
        while (a > 0) {
            int p = (a - 1) >> 1;
            float q = (float)(long long)g_qsplitI[p * NB + b] * QINV + bias[p];
            m = fminf(m, (a == 2 * p + 1) ? -q : q);
            a = p;
        }
        g_qnodeT[n * NB + b] = m;
        float qh = m + 0.5f;
#pragma unroll
        for (int c = 0; c < NC; c++) {
            float d = fminf((float)c * (1.0f / 20.0f) - qh, 0.0f);
            accs[c] = fmaf(d, d, accs[c]);
        }
    }

#pragma unroll
    for (int c = 0; c < NC; c++)
#pragma unroll
        for (int o = 16; o > 0; o >>= 1)
            accs[c] += __shfl_down_sync(0xffffffffu, accs[c], o);

    __shared__ float sW[8][NC];
    int w = tid >> 5, l = tid & 31;
    if (l == 0) {
#pragma unroll
        for (int c = 0; c < NC; c++) sW[w][c] = accs[c];
    }
    __syncthreads();
    if (tid < NC) {
        float s = 0.0f;
#pragma unroll
        for (int ww = 0; ww < 8; ww++) s += sW[ww][tid];
        float ac = (float)tid * (1.0f / 20.0f);
        g_ga[n * NC + tid] = 0.5f * ac * ac + 0.5f * s;
    }
}

// ================= kernel 3: the scan (warp-serial, interleaved, sAnode cache) =================
__device__ __forceinline__ void softmin_warp(int g, const float* sGa, const int* sK, float* sAgrp)
{
    int lane = threadIdx.x & 31;
    float kg = (float)sK[g];
    int c1 = 2 * g + 1, c2 = 2 * g + 2;
    float s;
    if (lane < NC) {
        float v = (1.0f - kg) * sGa[g * NC + lane];
        if (c1 < NN) v += (float)sK[c1] * sGa[c1 * NC + lane];
        if (c2 < NN) v += (float)sK[c2] * sGa[c2 * NC + lane];
        s = -100.0f * v;
    } else {
        s = -3.0e38f;
    }
    float m = s;
#pragma unroll
    for (int o = 16; o > 0; o >>= 1) m = fmaxf(m, __shfl_xor_sync(0xffffffffu, m, o));
    float e  = (lane < NC) ? __expf(s - m) : 0.0f;
    float ae = e * ((float)lane * (1.0f / 20.0f));
#pragma unroll
    for (int o = 16; o > 0; o >>= 1) {
        e  += __shfl_xor_sync(0xffffffffu, e, o);
        ae += __shfl_xor_sync(0xffffffffu, ae, o);
    }
    if (lane == 0) sAgrp[g] = ae / e;
}

__global__ __launch_bounds__(256)
void scan_kernel()
{
    __shared__ float sGa[NN * NC];   // 42924 B
    __shared__ float sAgrp[NN];
    __shared__ float sAnode[NN];
    __shared__ int   sK[NN];         // total 49056 B < 48KB static cap

    int tid = threadIdx.x;

    for (int i = tid; i < NN * NC; i += 256) sGa[i] = g_ga[i];
    for (int i = tid; i < NN; i += 256) sK[i] = 0;
    __syncthreads();

    // initial a_grp (k==0 -> own-row softmin); a_node == a_grp initially
    for (int i = tid; i < NN; i += 256) {
        const float* r = &sGa[i * NC];
        float m = -3.0e38f;
#pragma unroll
        for (int c = 0; c < NC; c++) m = fmaxf(m, -100.0f * r[c]);
        float su = 0.0f, asu = 0.0f;
#pragma unroll
        for (int c = 0; c < NC; c++) {
            float e = __expf(-100.0f * r[c] - m);
            su += e; asu += (float)c * (1.0f / 20.0f) * e;
        }
        float ag = asu / su;
        sAgrp[i]  = ag;
        sAnode[i] = ag;
    }
    __syncthreads();

    if (tid < 32) {
        // warp 0 runs the whole merge loop; interleaved mapping -> conflict-free LDS.
        int lane = tid;
        int applied = 0;
        for (;;) {
            float bv = -3.0e38f; int bi = NN;
#pragma unroll
            for (int i = 0; i < 16; i++) {
                int n = i * 32 + lane;           // lanes hit consecutive addrs
                if (n < NN) {
                    float an = sAnode[n];
                    float ap = (n == 0) ? 1.0f : sAnode[(n - 1) >> 1];  // broadcast-ish
                    float v = an - ap;
                    if (v > bv || (v == bv && n < bi)) { bv = v; bi = n; }
                }
            }
#pragma unroll
            for (int o = 16; o > 0; o >>= 1) {
                float ov = __shfl_down_sync(0xffffffffu, bv, o);
                int   oi = __shfl_down_sync(0xffffffffu, bi, o);
                if (ov > bv || (ov == bv && oi < bi)) { bv = ov; bi = oi; }
            }
            int t = (lane == 0) ? ((bv <= 1e-8f && bi > 0) ? bi : -1) : 0;
            t = __shfl_sync(0xffffffffu, t, 0);
            if (t < 0 || applied >= NN) break;   // fixed point / 512th body's merge discarded
            applied++;
            if (lane == 0) sK[t] += 1;
            __syncwarp();
            int p = (t - 1) >> 1;
            softmin_warp(p, sGa, sK, sAgrp);
            __syncwarp();
            softmin_warp(t, sGa, sK, sAgrp);
            __syncwarp();
            // incremental a_node refresh: exactly {p, t, sib(t), 2t+1, 2t+2}
            if (lane < 5) {
                int s0 = 2 * p + 1, s1 = 2 * p + 2;
                int sib = (s0 == t) ? s1 : s0;
                int m = (lane == 0) ? p
                      : (lane == 1) ? t
                      : (lane == 2) ? sib
                      : (lane == 3) ? 2 * t + 1
                                    : 2 * t + 2;
                if (m < NN) {
                    float an;
                    if (m == 0) an = sAgrp[0];
                    else {
                        float k = (float)sK[m];
                        an = (1.0f - k) * sAgrp[m] + k * sAgrp[(m - 1) >> 1];
                    }
                    sAnode[m] = an;
                }
            }
            __syncwarp();
        }
    }
    __syncthreads();

    for (int i = tid; i < NN; i += 256) g_anode[i] = sAnode[i];
}

// ================= kernel 4: transposed trajectory + distributed accumulator re-zero ====
// 256 blocks, one 32x32 tile each; coalesced load AND store.
__global__ __launch_bounds__(256)
void traj_kernel(float* __restrict__ out)
{
    __shared__ float tile[32][33];
    int tid = threadIdx.x;
    int tn = blockIdx.x >> 4, tb = blockIdx.x & 15;
    int n0 = tn * 32, b0 = tb * 32;

#pragma unroll
    for (int pass = 0; pass < 4; pass++) {
        int r = (tid >> 5) + pass * 8, c = tid & 31;
        int n = n0 + r;
        float v = 0.0f;
        if (n < NN) {
            float q = g_qnodeT[n * NB + b0 + c];          // coalesced over b
            v = fminf(fmaxf(q, 0.0f), g_anode[n]);
        }
        tile[r][c] = v;
    }
    __syncthreads();
#pragma unroll
    for (int pass = 0; pass < 4; pass++) {
        int r = (tid >> 5) + pass * 8, c = tid & 31;
        int n = n0 + c;
        if (n < NN) out[(b0 + r) * NN + n] = tile[c][r];  // coalesced over n
    }

    // re-zero fixed-point accumulator for next launch, spread over 256 blocks
    ulonglong2 z; z.x = 0ULL; z.y = 0ULL;
    ulonglong2* p = (ulonglong2*)g_qsplitI;
    for (int i = blockIdx.x * 256 + tid; i < NS * NB / 2; i += 256 * 256) p[i] = z;
}

// ---------------- launch ----------------
extern "C" void kernel_launch(void* const* d_in, const int* in_sizes, int n_in,
                              void* d_out, int out_size)
{
    const float* x = (const float*)d_in[0];
    const float* W = (const float*)d_in[1];
    const float* b = (const float*)d_in[2];
    // d_in[3] = max_depth (fixed at 8; shapes hardcoded)

    gemm_kernel<<<dim3(8, 8, 4), 256>>>(x, W);
    ga_kernel  <<<NN, 256>>>(b);
    scan_kernel<<<1, 256>>>();
    traj_kernel<<<256, 256>>>((float*)d_out);
}